// round 13
// baseline (speedup 1.0000x reference)
#include <cuda_runtime.h>
#include <cuda_bf16.h>
#include <math.h>
#include <stdint.h>

// LCNECortexLSTM B=65536, D=H=256 — mma.sync (HMMA bf16) split-precision pipeline.
// R13: K=32 chunks, ALL buffers double-buffered. Per round:
//   barrier; cp.async(c+1 -> bufs[p^1]); commit; wait_group(1);
//   transform raw[p]->A[p]; barrier; MMA(A[p],B[p]).
// A and B both prefetched one full round ahead (no exposed L2/DRAM latency).
// CTA tile 128x128, warp tile 64x32, __launch_bounds__(256,2) -> 2 CTAs/SM.
// D_fp32 = Ahi@Bhi + Ahi@Blo + Alo@Bhi.

#define BD 65536
#define HD 256
#define MT 128
#define NT 128
#define NTH 256
#define KCH 32

// per-buffer sizes: raw 16384 (fp32 128x32), A/B halves 8192 (bf16 128x32)
#define OFF_RAW 0
#define OFF_AHI 32768
#define OFF_ALO 49152
#define OFF_BHI 65536
#define OFF_BLO 81920
#define OFF_SCALE 98304
#define OFF_SHIFT 99328
#define OFF_WP 100352
#define OFF_PS 101376
#define SMEM_REQ 102912

// weight images: [mat][hi/lo], transposed [N][K], chunked 8x(256 rows x 32 k),
// 64B rows, XOR-16B swizzle (((n>>1)&3)<<4). mats: 0=Wx 1=Wh 2=Wf 3=WxWC 4=WxWi 5=WLC 6=Wo
__device__ __nv_bfloat16 g_Wimg[7][2][HD * HD];
__device__ float g_WxWi[HD * HD];
__device__ float g_WxWC[HD * HD];
__device__ float g_bxWi[HD];
__device__ float g_bxWC[HD];
__device__ float g_stats[6 * HD];
__device__ float g_scr1[(size_t)BD * HD];  // LC_raw
__device__ float g_scr2[(size_t)BD * HD];  // NE_raw

__device__ __forceinline__ float sigm(float x) { return 1.0f / (1.0f + expf(-x)); }
__device__ __forceinline__ float lky(float x) { return x > 0.0f ? x : 0.1f * x; }

__device__ __forceinline__ uint32_t smem_to_u32(const void* p) {
    uint32_t a;
    asm("{ .reg .u64 t; cvta.to.shared.u64 t, %1; cvt.u32.u64 %0, t; }" : "=r"(a) : "l"(p));
    return a;
}

__device__ __forceinline__ void ldsm_x4(uint32_t* r, uint32_t addr) {
    asm volatile("ldmatrix.sync.aligned.m8n8.x4.shared.b16 {%0,%1,%2,%3}, [%4];"
        : "=r"(r[0]), "=r"(r[1]), "=r"(r[2]), "=r"(r[3]) : "r"(addr));
}
__device__ __forceinline__ void ldsm_x2(uint32_t* r, uint32_t addr) {
    asm volatile("ldmatrix.sync.aligned.m8n8.x2.shared.b16 {%0,%1}, [%2];"
        : "=r"(r[0]), "=r"(r[1]) : "r"(addr));
}
__device__ __forceinline__ void mma_bf16(float* c, const uint32_t* a, const uint32_t* b) {
    asm volatile("mma.sync.aligned.m16n8k16.row.col.f32.bf16.bf16.f32 "
        "{%0,%1,%2,%3}, {%4,%5,%6,%7}, {%8,%9}, {%0,%1,%2,%3};"
        : "+f"(c[0]), "+f"(c[1]), "+f"(c[2]), "+f"(c[3])
        : "r"(a[0]), "r"(a[1]), "r"(a[2]), "r"(a[3]), "r"(b[0]), "r"(b[1]));
}
__device__ __forceinline__ void cp16(uint32_t dst, const void* src) {
    asm volatile("cp.async.cg.shared.global [%0], [%1], 16;" :: "r"(dst), "l"(src));
}
#define CP_COMMIT asm volatile("cp.async.commit_group;" ::: "memory")
#define CP_WAIT1 asm volatile("cp.async.wait_group 1;" ::: "memory")

__device__ __forceinline__ uint32_t pack_split(float a, float b, uint32_t& lo) {
    __nv_bfloat162 h = __floats2bfloat162_rn(a, b);
    __nv_bfloat162 l = __floats2bfloat162_rn(a - __low2float(h), b - __high2float(h));
    lo = *reinterpret_cast<uint32_t*>(&l);
    return *reinterpret_cast<uint32_t*>(&h);
}

// ---------------- kernel body macros ----------------

#define GEMM_PROLOG                                                           \
    extern __shared__ char dsm_[];                                            \
    char* smem = (char*)(((uintptr_t)dsm_ + 1023) & ~(uintptr_t)1023);        \
    const int tid = threadIdx.x, wid = tid >> 5, lane = tid & 31;             \
    const int wm = wid & 1, wn = wid >> 1;                                    \
    const int row0 = blockIdx.x * MT;                                         \
    const int ncol0 = blockIdx.y * NT;                                        \
    const uint32_t su = smem_to_u32(smem);                                    \
    char* sRAW = smem + OFF_RAW;                                              \
    char* sAhi = smem + OFF_AHI; char* sAlo = smem + OFF_ALO;                 \
    const uint32_t uRAW = su + OFF_RAW;                                       \
    const uint32_t uAhi = su + OFF_AHI, uAlo = su + OFF_ALO;                  \
    const uint32_t uBhi = su + OFF_BHI, uBlo = su + OFF_BLO;                  \
    float* sScale = (float*)(smem + OFF_SCALE);                               \
    float* sShift = (float*)(smem + OFF_SHIFT);                               \
    (void)sScale; (void)sShift; (void)sRAW; (void)sAlo;                       \
    float acc[4][4][4];                                                       \
    _Pragma("unroll") for (int i_ = 0; i_ < 4; i_++)                          \
        _Pragma("unroll") for (int j_ = 0; j_ < 4; j_++)                      \
            _Pragma("unroll") for (int q_ = 0; q_ < 4; q_++)                  \
                acc[i_][j_][q_] = 0.0f;

// cp.async raw fp32 A chunk (128 rows x 32 cols = 16KB) into raw[P]; XOR-16B swizzle by row.
#define A_CPASYNC(SRC, KB, P)                                                 \
    {                                                                         \
        const int r_ = tid >> 1;                                              \
        const int hb_ = (tid & 1) * 64;                                       \
        const uint32_t rb_ = uRAW + (uint32_t)(P) * 16384 + (uint32_t)r_ * 128; \
        const char* gs_ = (const char*)((SRC) + (size_t)(row0 + r_) * HD + (KB)); \
        _Pragma("unroll") for (int q = 0; q < 4; q++) {                       \
            uint32_t o_ = (uint32_t)(hb_ + q * 16);                           \
            cp16(rb_ + (o_ ^ ((r_ & 7) << 4)), gs_ + o_);                     \
        }                                                                     \
    }

// cp.async pre-swizzled B half-chunk (8KB hi + 8KB lo) into B[P].
#define B_CPASYNC(WHI, WLO, CH, P)                                            \
    {                                                                         \
        const char* bh_ = (const char*)(WHI) + (CH) * 16384 + ncol0 * 64;     \
        const char* bl_ = (const char*)(WLO) + (CH) * 16384 + ncol0 * 64;     \
        uint32_t o0_ = (uint32_t)tid * 16, o1_ = o0_ + 4096;                  \
        uint32_t db_ = (uint32_t)(P) * 8192;                                  \
        cp16(uBhi + db_ + o0_, bh_ + o0_);                                    \
        cp16(uBhi + db_ + o1_, bh_ + o1_);                                    \
        cp16(uBlo + db_ + o0_, bl_ + o0_);                                    \
        cp16(uBlo + db_ + o1_, bl_ + o1_);                                    \
    }

#define COMPUTE_CHUNK(P)                                                      \
    _Pragma("unroll") for (int ks = 0; ks < 2; ks++) {                        \
        uint32_t ah[4][4], al[4][4];                                          \
        _Pragma("unroll") for (int mi = 0; mi < 4; mi++) {                    \
            int r = wm * 64 + mi * 16 + (lane & 15);                          \
            int kb = ks * 32 + ((lane & 16) ? 16 : 0);                        \
            uint32_t sw = (uint32_t)(P) * 8192 + (uint32_t)r * 64 +           \
                          (uint32_t)(kb ^ (((r >> 1) & 3) << 4));             \
            ldsm_x4(ah[mi], uAhi + sw);                                       \
            ldsm_x4(al[mi], uAlo + sw);                                       \
        }                                                                     \
        _Pragma("unroll") for (int ni = 0; ni < 4; ni++) {                    \
            int l = lane & 15;                                                \
            int rn = wn * 32 + ni * 8 + (l & 7);                              \
            int kb = ks * 32 + ((l & 8) ? 16 : 0);                            \
            uint32_t sw = (uint32_t)(P) * 8192 + (uint32_t)rn * 64 +          \
                          (uint32_t)(kb ^ (((rn >> 1) & 3) << 4));            \
            uint32_t bh2[2], bl2[2];                                          \
            ldsm_x2(bh2, uBhi + sw);                                          \
            ldsm_x2(bl2, uBlo + sw);                                          \
            _Pragma("unroll") for (int mi = 0; mi < 4; mi++) {                \
                mma_bf16(acc[mi][ni], ah[mi], bh2);                           \
                mma_bf16(acc[mi][ni], ah[mi], bl2);                           \
                mma_bf16(acc[mi][ni], al[mi], bh2);                           \
            }                                                                 \
        }                                                                     \
    }

// transform helpers: thread owns row r = tid>>1, k-halves kh = (tid&1)*16, 4 float4s.
#define RAW_RD(P, r, kcol)                                                    \
    (*(const float4*)(sRAW + (P) * 16384 + (r) * 128 +                        \
                      (((kcol) * 4) ^ (((r) & 7) << 4))))

#define A_WR(P, r, kcol, h2, l2)                                              \
    {                                                                         \
        uint32_t ao_ = (uint32_t)(P) * 8192 + (uint32_t)(r) * 64 +            \
                       (uint32_t)(((kcol) * 2) ^ ((((r) >> 1) & 3) << 4));    \
        *(uint2*)(sAhi + ao_) = h2;                                           \
        *(uint2*)(sAlo + ao_) = l2;                                           \
    }

#define SPLIT4(av, h2, l2)                                                    \
    uint2 h2, l2;                                                             \
    h2.x = pack_split((av).x, (av).y, l2.x);                                  \
    h2.y = pack_split((av).z, (av).w, l2.y);

#define A_TRANS_PLAIN(P)                                                      \
    {                                                                         \
        const int r = tid >> 1, kh = (tid & 1) * 16;                          \
        _Pragma("unroll") for (int q = 0; q < 4; q++) {                       \
            int kcol = kh + q * 4;                                            \
            float4 av = RAW_RD(P, r, kcol);                                   \
            SPLIT4(av, h2, l2);                                               \
            A_WR(P, r, kcol, h2, l2);                                         \
        }                                                                     \
    }

#define A_TRANS_BN(OUT, KB, P)                                                \
    {                                                                         \
        const int r = tid >> 1, kh = (tid & 1) * 16;                          \
        _Pragma("unroll") for (int q = 0; q < 4; q++) {                       \
            int kcol = kh + q * 4;                                            \
            float4 sc = *(float4*)&sScale[(KB) + kcol];                       \
            float4 sh = *(float4*)&sShift[(KB) + kcol];                       \
            float4 av = RAW_RD(P, r, kcol);                                   \
            av.x = lky(fmaf(av.x, sc.x, sh.x));                               \
            av.y = lky(fmaf(av.y, sc.y, sh.y));                               \
            av.z = lky(fmaf(av.z, sc.z, sh.z));                               \
            av.w = lky(fmaf(av.w, sc.w, sh.w));                               \
            *(float4*)((OUT) + (size_t)(row0 + r) * HD + (KB) + kcol) = av;   \
            SPLIT4(av, h2, l2);                                               \
            A_WR(P, r, kcol, h2, l2);                                         \
        }                                                                     \
    }

#define A_TRANS_TP(OUT, LCP, NEP, KB, P)                                      \
    {                                                                         \
        const int r = tid >> 1, kh = (tid & 1) * 16;                          \
        _Pragma("unroll") for (int q = 0; q < 4; q++) {                       \
            int kcol = kh + q * 4;                                            \
            float4 sc = *(float4*)&sScale[(KB) + kcol];                       \
            float4 sh = *(float4*)&sShift[(KB) + kcol];                       \
            float4 wp = *(float4*)&sWP[(KB) + kcol];                          \
            size_t gx = (size_t)(row0 + r) * HD + (KB) + kcol;                \
            float4 av = RAW_RD(P, r, kcol);                                   \
            av.x = lky(fmaf(av.x, sc.x, sh.x));                               \
            av.y = lky(fmaf(av.y, sc.y, sh.y));                               \
            av.z = lky(fmaf(av.z, sc.z, sh.z));                               \
            av.w = lky(fmaf(av.w, sc.w, sh.w));                               \
            *(float4*)((OUT) + gx) = av;                                      \
            float4 lv = *(const float4*)((LCP) + gx);                         \
            float4 nv = *(const float4*)((NEP) + gx);                         \
            pval = fmaf(av.x + lv.x + nv.x, wp.x, pval);                      \
            pval = fmaf(av.y + lv.y + nv.y, wp.y, pval);                      \
            pval = fmaf(av.z + lv.z + nv.z, wp.z, pval);                      \
            pval = fmaf(av.w + lv.w + nv.w, wp.w, pval);                      \
            SPLIT4(av, h2, l2);                                               \
            A_WR(P, r, kcol, h2, l2);                                         \
        }                                                                     \
    }

// epilogue iteration: rr = global row, cb = global column (pair base)
#define EPI_BEGIN                                                             \
    _Pragma("unroll") for (int mi = 0; mi < 4; mi++) {                        \
        _Pragma("unroll") for (int h = 0; h < 2; h++) {                       \
            const int rr = row0 + wm * 64 + mi * 16 + (lane >> 2) + h * 8;    \
            _Pragma("unroll") for (int ni = 0; ni < 4; ni++) {                \
                const int cb = ncol0 + wn * 32 + ni * 8 + (lane & 3) * 2;     \
                float vx = acc[mi][ni][h * 2], vy = acc[mi][ni][h * 2 + 1];   \
                (void)cb;

#define EPI_END_STORE(OUT)                                                    \
                *(float2*)((OUT) + (size_t)rr * HD + cb) = make_float2(vx, vy); \
            } } }

#define EPI_END_ACC                                                           \
                acc[mi][ni][h * 2] = vx; acc[mi][ni][h * 2 + 1] = vy;         \
            } } }

#define STATS_DECL                                                            \
    float ssum[4][2], ssq[4][2];                                              \
    _Pragma("unroll") for (int i_ = 0; i_ < 4; i_++) {                        \
        ssum[i_][0] = ssum[i_][1] = 0.0f; ssq[i_][0] = ssq[i_][1] = 0.0f; }

#define STATS_ACC                                                             \
    ssum[ni][0] += vx; ssq[ni][0] += vx * vx;                                 \
    ssum[ni][1] += vy; ssq[ni][1] += vy * vy;

#define STATS_REDUCE(SIDX)                                                    \
    _Pragma("unroll") for (int ni = 0; ni < 4; ni++) {                        \
        _Pragma("unroll") for (int c2 = 0; c2 < 2; c2++) {                    \
            float s_ = ssum[ni][c2], q_ = ssq[ni][c2];                        \
            s_ += __shfl_xor_sync(~0u, s_, 4);  q_ += __shfl_xor_sync(~0u, q_, 4);  \
            s_ += __shfl_xor_sync(~0u, s_, 8);  q_ += __shfl_xor_sync(~0u, q_, 8);  \
            s_ += __shfl_xor_sync(~0u, s_, 16); q_ += __shfl_xor_sync(~0u, q_, 16); \
            if (lane < 4) {                                                   \
                int col = ncol0 + wn * 32 + ni * 8 + lane * 2 + c2;           \
                atomicAdd(&g_stats[(SIDX) * HD + col], s_);                   \
                atomicAdd(&g_stats[((SIDX) + 1) * HD + col], q_);             \
            } } }

#define BN_PREP(SIDX, G, B)                                                   \
    {                                                                         \
        float m_ = g_stats[(SIDX) * HD + tid] * (1.0f / (float)BD);           \
        float e2_ = g_stats[((SIDX) + 1) * HD + tid] * (1.0f / (float)BD);    \
        float rs_ = rsqrtf(e2_ - m_ * m_ + 1e-5f);                            \
        float sc_ = rs_ * (G)[tid];                                           \
        sScale[tid] = sc_;                                                    \
        sShift[tid] = (B)[tid] - m_ * sc_;                                    \
    }

#define BIAS4(DST, SRCP)                                                      \
    float2 DST[4];                                                            \
    _Pragma("unroll") for (int i_ = 0; i_ < 4; i_++)                          \
        DST[i_] = *(const float2*)((SRCP) + ncol0 + wn * 32 + i_ * 8 + (lane & 3) * 2);

// ---------------- prep kernels ----------------

__global__ void __launch_bounds__(NTH) k0_prep(
    const float* __restrict__ Wx, const float* __restrict__ bx,
    const float* __restrict__ Wi, const float* __restrict__ bi,
    const float* __restrict__ WC, const float* __restrict__ bC) {
    int h = threadIdx.x;
    if (blockIdx.x < HD) {
        __shared__ float sA[HD];
        sA[h] = Wx[blockIdx.x * HD + h];
        __syncthreads();
        float aI = 0.0f, aC = 0.0f;
#pragma unroll 4
        for (int k = 0; k < HD; k++) {
            float a = sA[k];
            aI = fmaf(a, Wi[k * HD + h], aI);
            aC = fmaf(a, WC[k * HD + h], aC);
        }
        g_WxWi[blockIdx.x * HD + h] = aI;
        g_WxWC[blockIdx.x * HD + h] = aC;
    } else {
        float aI = bi[h], aC = bC[h];
        for (int k = 0; k < HD; k++) {
            float a = bx[k];
            aI = fmaf(a, Wi[k * HD + h], aI);
            aC = fmaf(a, WC[k * HD + h], aC);
        }
        g_bxWi[h] = aI;
        g_bxWC[h] = aC;
#pragma unroll
        for (int s = 0; s < 6; s++) g_stats[s * HD + h] = 0.0f;
    }
}

// weights -> transposed [N][K] bf16 hi/lo, chunked by K=32 (8 chunks),
// 64B rows with XOR-16B swizzle ((n>>1)&3)<<4
__global__ void __launch_bounds__(NTH) kW(
    const float* __restrict__ Wx, const float* __restrict__ Wh,
    const float* __restrict__ Wf, const float* __restrict__ WLC,
    const float* __restrict__ Wo) {
    int k = blockIdx.x, m = blockIdx.y, n = threadIdx.x;
    const float* src;
    switch (m) {
        case 0: src = Wx; break;
        case 1: src = Wh; break;
        case 2: src = Wf; break;
        case 3: src = g_WxWC; break;
        case 4: src = g_WxWi; break;
        case 5: src = WLC; break;
        default: src = Wo; break;
    }
    float val = src[k * HD + n];
    __nv_bfloat16 h = __float2bfloat16(val);
    __nv_bfloat16 l = __float2bfloat16(val - __bfloat162float(h));
    int chunk = k >> 5, kk = k & 31;
    uint32_t off = (uint32_t)chunk * 16384 + (uint32_t)n * 64 +
                   (uint32_t)((kk * 2) ^ (((n >> 1) & 3) << 4));
    *(__nv_bfloat16*)((char*)g_Wimg[m][0] + off) = h;
    *(__nv_bfloat16*)((char*)g_Wimg[m][1] + off) = l;
}

// ---------------- GEMM kernels ----------------

// k1a: LC_raw = X@Wx + pLC@Wh + (bx+bh) -> g_scr1; stats0. 16 rounds.
__global__ void __launch_bounds__(NTH, 2) k1a(
    const float* __restrict__ X, const float* __restrict__ pLC,
    const float* __restrict__ bx, const float* __restrict__ bh_) {
    GEMM_PROLOG;
    A_CPASYNC(X, 0, 0);
    B_CPASYNC(g_Wimg[0][0], g_Wimg[0][1], 0, 0);
    CP_COMMIT;
#pragma unroll 1
    for (int c = 0; c < 16; c++) {
        int p = c & 1;
        __syncthreads();
        if (c + 1 < 16) {
            const float* nsrc = (c + 1 < 8) ? X : pLC;
            int nmat = (c + 1 < 8) ? 0 : 1;
            A_CPASYNC(nsrc, ((c + 1) & 7) * KCH, p ^ 1);
            B_CPASYNC(g_Wimg[nmat][0], g_Wimg[nmat][1], (c + 1) & 7, p ^ 1);
        }
        CP_COMMIT;
        CP_WAIT1;
        A_TRANS_PLAIN(p);
        __syncthreads();
        COMPUTE_CHUNK(p);
    }
    BIAS4(b1, bx); BIAS4(b2, bh_);
    STATS_DECL;
    EPI_BEGIN;
    vx += b1[ni].x + b2[ni].x;
    vy += b1[ni].y + b2[ni].y;
    STATS_ACC;
    EPI_END_STORE(g_scr1);
    STATS_REDUCE(0);
}

// k1b: base = sigmoid(pC@Wf+bf)*cell + X@WxWC + bxWC -> sec2 (mid-transform at c==7). 16 rounds.
__global__ void __launch_bounds__(NTH, 2) k1b(
    const float* __restrict__ pC, const float* __restrict__ X,
    const float* __restrict__ bf_, const float* __restrict__ cell, float* out) {
    GEMM_PROLOG;
    A_CPASYNC(pC, 0, 0);
    B_CPASYNC(g_Wimg[2][0], g_Wimg[2][1], 0, 0);
    CP_COMMIT;
#pragma unroll 1
    for (int c = 0; c < 16; c++) {
        int p = c & 1;
        __syncthreads();
        if (c + 1 < 16) {
            const float* nsrc = (c + 1 < 8) ? pC : X;
            int nmat = (c + 1 < 8) ? 2 : 3;
            A_CPASYNC(nsrc, ((c + 1) & 7) * KCH, p ^ 1);
            B_CPASYNC(g_Wimg[nmat][0], g_Wimg[nmat][1], (c + 1) & 7, p ^ 1);
        }
        CP_COMMIT;
        CP_WAIT1;
        A_TRANS_PLAIN(p);
        __syncthreads();
        COMPUTE_CHUNK(p);
        if (c == 7) {
            BIAS4(bfv, bf_);
            EPI_BEGIN;
            float2 cv = *(const float2*)(cell + (size_t)rr * HD + cb);
            vx = sigm(vx + bfv[ni].x) * cv.x;
            vy = sigm(vy + bfv[ni].y) * cv.y;
            EPI_END_ACC;
        }
    }
    BIAS4(bb, g_bxWC);
    EPI_BEGIN;
    vx += bb[ni].x;
    vy += bb[ni].y;
    EPI_END_STORE(out);
}

// k1c: igate = sigmoid(X@WxWi + bxWi) -> sec3. 8 rounds.
__global__ void __launch_bounds__(NTH, 2) k1c(const float* __restrict__ X, float* out) {
    GEMM_PROLOG;
    A_CPASYNC(X, 0, 0);
    B_CPASYNC(g_Wimg[4][0], g_Wimg[4][1], 0, 0);
    CP_COMMIT;
#pragma unroll 1
    for (int c = 0; c < 8; c++) {
        int p = c & 1;
        __syncthreads();
        if (c + 1 < 8) {
            A_CPASYNC(X, (c + 1) * KCH, p ^ 1);
            B_CPASYNC(g_Wimg[4][0], g_Wimg[4][1], c + 1, p ^ 1);
        }
        CP_COMMIT;
        CP_WAIT1;
        A_TRANS_PLAIN(p);
        __syncthreads();
        COMPUTE_CHUNK(p);
    }
    BIAS4(bb, g_bxWi);
    EPI_BEGIN;
    vx = sigm(vx + bb[ni].x);
    vy = sigm(vy + bb[ni].y);
    EPI_END_STORE(out);
}

// k2: LC_t = leaky(bn1(g_scr1)) -> sec0; NE_raw = LC_t@WLC + bLC -> g_scr2; stats2. 8 rounds.
__global__ void __launch_bounds__(NTH, 2) k2(
    float* out_lct, const float* __restrict__ bLC,
    const float* __restrict__ g1, const float* __restrict__ be1) {
    GEMM_PROLOG;
    BN_PREP(0, g1, be1);
    A_CPASYNC(g_scr1, 0, 0);
    B_CPASYNC(g_Wimg[5][0], g_Wimg[5][1], 0, 0);
    CP_COMMIT;
#pragma unroll 1
    for (int c = 0; c < 8; c++) {
        int p = c & 1;
        __syncthreads();
        if (c + 1 < 8) {
            A_CPASYNC(g_scr1, (c + 1) * KCH, p ^ 1);
            B_CPASYNC(g_Wimg[5][0], g_Wimg[5][1], c + 1, p ^ 1);
        }
        CP_COMMIT;
        CP_WAIT1;
        A_TRANS_BN(out_lct, c * KCH, p);
        __syncthreads();
        COMPUTE_CHUNK(p);
    }
    BIAS4(bb, bLC);
    STATS_DECL;
    EPI_BEGIN;
    vx += bb[ni].x;
    vy += bb[ni].y;
    STATS_ACC;
    EPI_END_STORE(g_scr2);
    STATS_REDUCE(2);
}

// k3: NE_t = leaky(bn2(g_scr2)) -> sec1; new_cell = base + ig*0.1*(NE_t@WLC+bLC) -> sec4; stats4.
__global__ void __launch_bounds__(NTH, 2) k3(
    float* out_nc, float* out_net, const float* __restrict__ bLC,
    const float* __restrict__ base, const float* __restrict__ ig,
    const float* __restrict__ g2, const float* __restrict__ be2) {
    GEMM_PROLOG;
    BN_PREP(2, g2, be2);
    A_CPASYNC(g_scr2, 0, 0);
    B_CPASYNC(g_Wimg[5][0], g_Wimg[5][1], 0, 0);
    CP_COMMIT;
#pragma unroll 1
    for (int c = 0; c < 8; c++) {
        int p = c & 1;
        __syncthreads();
        if (c + 1 < 8) {
            A_CPASYNC(g_scr2, (c + 1) * KCH, p ^ 1);
            B_CPASYNC(g_Wimg[5][0], g_Wimg[5][1], c + 1, p ^ 1);
        }
        CP_COMMIT;
        CP_WAIT1;
        A_TRANS_BN(out_net, c * KCH, p);
        __syncthreads();
        COMPUTE_CHUNK(p);
    }
    BIAS4(bb, bLC);
    STATS_DECL;
    EPI_BEGIN;
    float2 bv = *(const float2*)(base + (size_t)rr * HD + cb);
    float2 iv = *(const float2*)(ig + (size_t)rr * HD + cb);
    vx = fmaf(iv.x * 0.1f, vx + bb[ni].x, bv.x);
    vy = fmaf(iv.y * 0.1f, vy + bb[ni].y, bv.y);
    STATS_ACC;
    EPI_END_STORE(out_nc);
    STATS_REDUCE(4);
}

// k4: C_t = leaky(bn3(sec4)) -> sec2; p = (LC_t+C_t+NE_t)@WP;
//     Pupil = sigmoid(C_t@Wo+bo)*(p+bP) -> sec3.
__global__ void __launch_bounds__(NTH, 2) k4(
    const float* __restrict__ ncell, float* out_ct,
    const float* __restrict__ lct, const float* __restrict__ net,
    const float* __restrict__ bo, const float* __restrict__ WP,
    const float* __restrict__ bP, const float* __restrict__ g3,
    const float* __restrict__ be3, float* out_pupil) {
    GEMM_PROLOG;
    BN_PREP(4, g3, be3);
    float* sWP = (float*)(smem + OFF_WP);
    float* p_s = (float*)(smem + OFF_PS);
    sWP[tid] = WP[tid];
    if (tid < MT) p_s[tid] = 0.0f;
    float pval = 0.0f;
    A_CPASYNC(ncell, 0, 0);
    B_CPASYNC(g_Wimg[6][0], g_Wimg[6][1], 0, 0);
    CP_COMMIT;
#pragma unroll 1
    for (int c = 0; c < 8; c++) {
        int p = c & 1;
        __syncthreads();
        if (c + 1 < 8) {
            A_CPASYNC(ncell, (c + 1) * KCH, p ^ 1);
            B_CPASYNC(g_Wimg[6][0], g_Wimg[6][1], c + 1, p ^ 1);
        }
        CP_COMMIT;
        CP_WAIT1;
        A_TRANS_TP(out_ct, lct, net, c * KCH, p);
        __syncthreads();
        COMPUTE_CHUNK(p);
    }
    atomicAdd(&p_s[tid >> 1], pval);
    __syncthreads();
    float bP0 = bP[0];
    BIAS4(bb, bo);
    EPI_BEGIN;
    float pr = p_s[rr - row0] + bP0;
    vx = sigm(vx + bb[ni].x) * pr;
    vy = sigm(vy + bb[ni].y) * pr;
    EPI_END_STORE(out_pupil);
}

// ---------------- launch ----------------

extern "C" void kernel_launch(void* const* d_in, const int* in_sizes, int n_in,
                              void* d_out, int out_size) {
    (void)in_sizes; (void)n_in; (void)out_size;
    const float* X    = (const float*)d_in[0];
    const float* pLC  = (const float*)d_in[1];
    const float* pC   = (const float*)d_in[2];
    const float* cell = (const float*)d_in[3];
    const float* Wx = (const float*)d_in[4];   const float* bx = (const float*)d_in[5];
    const float* Wh = (const float*)d_in[6];   const float* bh = (const float*)d_in[7];
    const float* WLC = (const float*)d_in[8];  const float* bLC = (const float*)d_in[9];
    const float* WC = (const float*)d_in[10];  const float* bC = (const float*)d_in[11];
    const float* WP = (const float*)d_in[12];  const float* bP = (const float*)d_in[13];
    const float* Wf = (const float*)d_in[14];  const float* bf = (const float*)d_in[15];
    const float* Wi = (const float*)d_in[16];  const float* bi = (const float*)d_in[17];
    const float* Wo = (const float*)d_in[18];  const float* bo = (const float*)d_in[19];
    const float* g1 = (const float*)d_in[20];  const float* be1 = (const float*)d_in[21];
    const float* g2 = (const float*)d_in[22];  const float* be2 = (const float*)d_in[23];
    const float* g3 = (const float*)d_in[24];  const float* be3 = (const float*)d_in[25];

    float* o = (float*)d_out;
    const size_t SEC = (size_t)BD * HD;
    float* sLC = o;            // LC_t   (written by k2)
    float* sNE = o + SEC;      // NE_t   (written by k3)
    float* sCT = o + 2 * SEC;  // C_t    (base until k3 consumes it; k4 writes C_t)
    float* sPU = o + 3 * SEC;  // Pupil  (igate until k3; k4 writes Pupil)
    float* sNC = o + 4 * SEC;  // new_cell (written by k3)

    // idempotent; called every time (no static guards per harness contract)
    cudaFuncSetAttribute(k1a, cudaFuncAttributeMaxDynamicSharedMemorySize, SMEM_REQ);
    cudaFuncSetAttribute(k1b, cudaFuncAttributeMaxDynamicSharedMemorySize, SMEM_REQ);
    cudaFuncSetAttribute(k1c, cudaFuncAttributeMaxDynamicSharedMemorySize, SMEM_REQ);
    cudaFuncSetAttribute(k2, cudaFuncAttributeMaxDynamicSharedMemorySize, SMEM_REQ);
    cudaFuncSetAttribute(k3, cudaFuncAttributeMaxDynamicSharedMemorySize, SMEM_REQ);
    cudaFuncSetAttribute(k4, cudaFuncAttributeMaxDynamicSharedMemorySize, SMEM_REQ);

    dim3 blk(NTH);
    dim3 grd(BD / MT, HD / NT);

    k0_prep<<<HD + 1, NTH>>>(Wx, bx, Wi, bi, WC, bC);
    kW<<<dim3(HD, 7), NTH>>>(Wx, Wh, Wf, WLC, Wo);
    k1a<<<grd, blk, SMEM_REQ>>>(X, pLC, bx, bh);
    k1b<<<grd, blk, SMEM_REQ>>>(pC, X, bf, cell, sCT);
    k1c<<<grd, blk, SMEM_REQ>>>(X, sPU);
    k2<<<grd, blk, SMEM_REQ>>>(sLC, bLC, g1, be1);
    k3<<<grd, blk, SMEM_REQ>>>(sNC, sNE, bLC, sCT, sPU, g2, be2);
    k4<<<grd, blk, SMEM_REQ>>>(sNC, sCT, sLC, sNE, bo, WP, bP, g3, be3, sPU);
}

// round 14
// speedup vs baseline: 1.1529x; 1.1529x over previous
#include <cuda_runtime.h>
#include <cuda_bf16.h>
#include <math.h>
#include <stdint.h>

// LCNECortexLSTM B=65536, D=H=256 — mma.sync (HMMA bf16) split-precision pipeline.
// R14 = R12 structure (K=64 chunks, cp.async staged raw A + B, 2 CTAs/SM) with
// the MMA issue order fixed: term-major inner loop (dependence distance 4) and
// non-volatile MMA asm so ptxas can interleave independent accumulator chains.
// D_fp32 = Ahi@Bhi + Ahi@Blo + Alo@Bhi.

#define BD 65536
#define HD 256
#define MT 128
#define NT 128
#define NTH 256

#define OFF_RAW 0
#define OFF_AHI 32768
#define OFF_ALO 49152
#define OFF_BHI 65536
#define OFF_BLO 81920
#define OFF_SCALE 98304
#define OFF_SHIFT 99328
#define OFF_WP 100352
#define OFF_PS 101376
#define SMEM_REQ 102912

// weight images: [mat][hi/lo], transposed [N][K], chunked 4x(256 rows x 64 k),
// 128B rows with XOR-16B swizzle. mats: 0=Wx 1=Wh 2=Wf 3=WxWC 4=WxWi 5=WLC 6=Wo
__device__ __nv_bfloat16 g_Wimg[7][2][HD * HD];
__device__ float g_WxWi[HD * HD];
__device__ float g_WxWC[HD * HD];
__device__ float g_bxWi[HD];
__device__ float g_bxWC[HD];
__device__ float g_stats[6 * HD];
__device__ float g_scr1[(size_t)BD * HD];  // LC_raw
__device__ float g_scr2[(size_t)BD * HD];  // NE_raw

__device__ __forceinline__ float sigm(float x) { return 1.0f / (1.0f + expf(-x)); }
__device__ __forceinline__ float lky(float x) { return x > 0.0f ? x : 0.1f * x; }

__device__ __forceinline__ uint32_t smem_to_u32(const void* p) {
    uint32_t a;
    asm("{ .reg .u64 t; cvta.to.shared.u64 t, %1; cvt.u32.u64 %0, t; }" : "=r"(a) : "l"(p));
    return a;
}

__device__ __forceinline__ void ldsm_x4(uint32_t* r, uint32_t addr) {
    asm volatile("ldmatrix.sync.aligned.m8n8.x4.shared.b16 {%0,%1,%2,%3}, [%4];"
        : "=r"(r[0]), "=r"(r[1]), "=r"(r[2]), "=r"(r[3]) : "r"(addr));
}
__device__ __forceinline__ void ldsm_x2(uint32_t* r, uint32_t addr) {
    asm volatile("ldmatrix.sync.aligned.m8n8.x2.shared.b16 {%0,%1}, [%2];"
        : "=r"(r[0]), "=r"(r[1]) : "r"(addr));
}
// NOTE: not volatile — register-only in/outs; ordering within each accumulator
// chain is enforced by the "+f" data dependence, and ptxas is free to
// interleave independent (mi,ni) chains for tensor-pipe utilization.
__device__ __forceinline__ void mma_bf16(float* c, const uint32_t* a, const uint32_t* b) {
    asm("mma.sync.aligned.m16n8k16.row.col.f32.bf16.bf16.f32 "
        "{%0,%1,%2,%3}, {%4,%5,%6,%7}, {%8,%9}, {%0,%1,%2,%3};"
        : "+f"(c[0]), "+f"(c[1]), "+f"(c[2]), "+f"(c[3])
        : "r"(a[0]), "r"(a[1]), "r"(a[2]), "r"(a[3]), "r"(b[0]), "r"(b[1]));
}
__device__ __forceinline__ void cp16(uint32_t dst, const void* src) {
    asm volatile("cp.async.cg.shared.global [%0], [%1], 16;" :: "r"(dst), "l"(src));
}

__device__ __forceinline__ uint32_t pack_split(float a, float b, uint32_t& lo) {
    __nv_bfloat162 h = __floats2bfloat162_rn(a, b);
    __nv_bfloat162 l = __floats2bfloat162_rn(a - __low2float(h), b - __high2float(h));
    lo = *reinterpret_cast<uint32_t*>(&l);
    return *reinterpret_cast<uint32_t*>(&h);
}

// ---------------- kernel body macros ----------------

#define GEMM_PROLOG                                                           \
    extern __shared__ char dsm_[];                                            \
    char* smem = (char*)(((uintptr_t)dsm_ + 1023) & ~(uintptr_t)1023);        \
    const int tid = threadIdx.x, wid = tid >> 5, lane = tid & 31;             \
    const int wm = wid & 1, wn = wid >> 1;                                    \
    const int row0 = blockIdx.x * MT;                                         \
    const int ncol0 = blockIdx.y * NT;                                        \
    const uint32_t su = smem_to_u32(smem);                                    \
    char* sRAW = smem + OFF_RAW;                                              \
    char* sAhi = smem + OFF_AHI; char* sAlo = smem + OFF_ALO;                 \
    const uint32_t uRAW = su + OFF_RAW;                                       \
    const uint32_t uAhi = su + OFF_AHI, uAlo = su + OFF_ALO;                  \
    const uint32_t uBhi = su + OFF_BHI, uBlo = su + OFF_BLO;                  \
    float* sScale = (float*)(smem + OFF_SCALE);                               \
    float* sShift = (float*)(smem + OFF_SHIFT);                               \
    (void)sScale; (void)sShift; (void)sRAW; (void)sAlo;                       \
    float acc[4][4][4];                                                       \
    _Pragma("unroll") for (int i_ = 0; i_ < 4; i_++)                          \
        _Pragma("unroll") for (int j_ = 0; j_ < 4; j_++)                      \
            _Pragma("unroll") for (int q_ = 0; q_ < 4; q_++)                  \
                acc[i_][j_][q_] = 0.0f;

// cp.async one raw fp32 A chunk (128 rows x 64 cols) into sRAW; commits a group.
#define A_CPASYNC(SRC, KB)                                                    \
    {                                                                         \
        const int pr_ = tid >> 4, ps_ = (tid & 15) * 16;                      \
        _Pragma("unroll") for (int ii = 0; ii < 8; ii++) {                    \
            int r_ = pr_ + ii * 16;                                           \
            cp16(uRAW + (uint32_t)r_ * 256 + ps_,                             \
                 (const char*)((SRC) + (size_t)(row0 + r_) * HD + (KB)) + ps_); \
        }                                                                     \
        asm volatile("cp.async.commit_group;" ::: "memory");                  \
    }

// cp.async one pre-swizzled B half-chunk (16KB hi + 16KB lo); commits a group.
#define B_CPASYNC(WHI, WLO, CH)                                               \
    {                                                                         \
        const char* bh_ = (const char*)((WHI) + (CH) * 16384 + ncol0 * 64);   \
        const char* bl_ = (const char*)((WLO) + (CH) * 16384 + ncol0 * 64);   \
        _Pragma("unroll") for (int i = 0; i < 4; i++) {                       \
            uint32_t o_ = (uint32_t)(i * NTH + tid) * 16;                     \
            cp16(uBhi + o_, bh_ + o_);                                        \
            cp16(uBlo + o_, bl_ + o_);                                        \
        }                                                                     \
        asm volatile("cp.async.commit_group;" ::: "memory");                  \
    }

#define PIPE_WAIT_SYNC                                                        \
    asm volatile("cp.async.wait_group 0;" ::: "memory");                      \
    __syncthreads();

// term-major inner loops: chained MMAs to the same accumulator are separated
// by 4 independent MMAs.
#define COMPUTE_CHUNK                                                         \
    _Pragma("unroll") for (int ks = 0; ks < 4; ks++) {                        \
        uint32_t ah[4][4], al[4][4];                                          \
        _Pragma("unroll") for (int mi = 0; mi < 4; mi++) {                    \
            int r = wm * 64 + mi * 16 + (lane & 15);                          \
            int kb = ks * 32 + ((lane & 16) ? 16 : 0);                        \
            uint32_t sw = (uint32_t)r * 128 + (kb ^ ((r & 7) << 4));          \
            ldsm_x4(ah[mi], uAhi + sw);                                       \
            ldsm_x4(al[mi], uAlo + sw);                                       \
        }                                                                     \
        _Pragma("unroll") for (int ni = 0; ni < 4; ni++) {                    \
            int l = lane & 15;                                                \
            int rn = wn * 32 + ni * 8 + (l & 7);                              \
            int kb = ks * 32 + ((l & 8) ? 16 : 0);                            \
            uint32_t sw = (uint32_t)rn * 128 + (kb ^ ((rn & 7) << 4));        \
            uint32_t bh2[2], bl2[2];                                          \
            ldsm_x2(bh2, uBhi + sw);                                          \
            ldsm_x2(bl2, uBlo + sw);                                          \
            _Pragma("unroll") for (int mi = 0; mi < 4; mi++)                  \
                mma_bf16(acc[mi][ni], ah[mi], bh2);                           \
            _Pragma("unroll") for (int mi = 0; mi < 4; mi++)                  \
                mma_bf16(acc[mi][ni], ah[mi], bl2);                           \
            _Pragma("unroll") for (int mi = 0; mi < 4; mi++)                  \
                mma_bf16(acc[mi][ni], al[mi], bh2);                           \
        }                                                                     \
    }

#define SPLIT_STORE(av, r, cc)                                                \
    {                                                                         \
        uint2 h2, l2;                                                         \
        h2.x = pack_split((av).x, (av).y, l2.x);                              \
        h2.y = pack_split((av).z, (av).w, l2.y);                              \
        uint32_t off = (uint32_t)(r) * 128 + (((cc) * 2) ^ (((r) & 7) << 4)); \
        *(uint2*)(sAhi + off) = h2;                                           \
        *(uint2*)(sAlo + off) = l2;                                           \
    }

// transforms read the raw chunk from SMEM (cp.async-staged)
#define A_TRANS_PLAIN                                                         \
    {                                                                         \
        const int cr = tid >> 4, cc = (tid & 15) * 4;                         \
        _Pragma("unroll") for (int ii = 0; ii < 8; ii++) {                    \
            const int r = cr + ii * 16;                                       \
            float4 av = *(const float4*)(sRAW + r * 256 + cc * 4);            \
            SPLIT_STORE(av, r, cc);                                           \
        }                                                                     \
    }

#define A_TRANS_BN(OUT, KB)                                                   \
    {                                                                         \
        const int cr = tid >> 4, cc = (tid & 15) * 4;                         \
        float4 sc = *(float4*)&sScale[(KB) + cc];                             \
        float4 sh = *(float4*)&sShift[(KB) + cc];                             \
        _Pragma("unroll") for (int ii = 0; ii < 8; ii++) {                    \
            const int r = cr + ii * 16;                                       \
            float4 av = *(const float4*)(sRAW + r * 256 + cc * 4);            \
            av.x = lky(fmaf(av.x, sc.x, sh.x));                               \
            av.y = lky(fmaf(av.y, sc.y, sh.y));                               \
            av.z = lky(fmaf(av.z, sc.z, sh.z));                               \
            av.w = lky(fmaf(av.w, sc.w, sh.w));                               \
            *(float4*)((OUT) + (size_t)(row0 + r) * HD + (KB) + cc) = av;     \
            SPLIT_STORE(av, r, cc);                                           \
        }                                                                     \
    }

#define A_TRANS_TP(OUT, LCP, NEP, KB)                                         \
    {                                                                         \
        const int cr = tid >> 4, cc = (tid & 15) * 4;                         \
        float4 sc = *(float4*)&sScale[(KB) + cc];                             \
        float4 sh = *(float4*)&sShift[(KB) + cc];                             \
        float4 wp = *(float4*)&sWP[(KB) + cc];                                \
        _Pragma("unroll") for (int ii = 0; ii < 8; ii++) {                    \
            const int r = cr + ii * 16;                                       \
            size_t gx = (size_t)(row0 + r) * HD + (KB) + cc;                  \
            float4 av = *(const float4*)(sRAW + r * 256 + cc * 4);            \
            av.x = lky(fmaf(av.x, sc.x, sh.x));                               \
            av.y = lky(fmaf(av.y, sc.y, sh.y));                               \
            av.z = lky(fmaf(av.z, sc.z, sh.z));                               \
            av.w = lky(fmaf(av.w, sc.w, sh.w));                               \
            *(float4*)((OUT) + gx) = av;                                      \
            float4 lv = *(const float4*)((LCP) + gx);                         \
            float4 nv = *(const float4*)((NEP) + gx);                         \
            pv[ii] = fmaf(av.x + lv.x + nv.x, wp.x, pv[ii]);                  \
            pv[ii] = fmaf(av.y + lv.y + nv.y, wp.y, pv[ii]);                  \
            pv[ii] = fmaf(av.z + lv.z + nv.z, wp.z, pv[ii]);                  \
            pv[ii] = fmaf(av.w + lv.w + nv.w, wp.w, pv[ii]);                  \
            SPLIT_STORE(av, r, cc);                                           \
        }                                                                     \
    }

// epilogue iteration: rr = global row, cb = global column (pair base)
#define EPI_BEGIN                                                             \
    _Pragma("unroll") for (int mi = 0; mi < 4; mi++) {                        \
        _Pragma("unroll") for (int h = 0; h < 2; h++) {                       \
            const int rr = row0 + wm * 64 + mi * 16 + (lane >> 2) + h * 8;    \
            _Pragma("unroll") for (int ni = 0; ni < 4; ni++) {                \
                const int cb = ncol0 + wn * 32 + ni * 8 + (lane & 3) * 2;     \
                float vx = acc[mi][ni][h * 2], vy = acc[mi][ni][h * 2 + 1];   \
                (void)cb;

#define EPI_END_STORE(OUT)                                                    \
                *(float2*)((OUT) + (size_t)rr * HD + cb) = make_float2(vx, vy); \
            } } }

#define EPI_END_ACC                                                           \
                acc[mi][ni][h * 2] = vx; acc[mi][ni][h * 2 + 1] = vy;         \
            } } }

#define STATS_DECL                                                            \
    float ssum[4][2], ssq[4][2];                                              \
    _Pragma("unroll") for (int i_ = 0; i_ < 4; i_++) {                        \
        ssum[i_][0] = ssum[i_][1] = 0.0f; ssq[i_][0] = ssq[i_][1] = 0.0f; }

#define STATS_ACC                                                             \
    ssum[ni][0] += vx; ssq[ni][0] += vx * vx;                                 \
    ssum[ni][1] += vy; ssq[ni][1] += vy * vy;

#define STATS_REDUCE(SIDX)                                                    \
    _Pragma("unroll") for (int ni = 0; ni < 4; ni++) {                        \
        _Pragma("unroll") for (int c2 = 0; c2 < 2; c2++) {                    \
            float s_ = ssum[ni][c2], q_ = ssq[ni][c2];                        \
            s_ += __shfl_xor_sync(~0u, s_, 4);  q_ += __shfl_xor_sync(~0u, q_, 4);  \
            s_ += __shfl_xor_sync(~0u, s_, 8);  q_ += __shfl_xor_sync(~0u, q_, 8);  \
            s_ += __shfl_xor_sync(~0u, s_, 16); q_ += __shfl_xor_sync(~0u, q_, 16); \
            if (lane < 4) {                                                   \
                int col = ncol0 + wn * 32 + ni * 8 + lane * 2 + c2;           \
                atomicAdd(&g_stats[(SIDX) * HD + col], s_);                   \
                atomicAdd(&g_stats[((SIDX) + 1) * HD + col], q_);             \
            } } }

#define BN_PREP(SIDX, G, B)                                                   \
    {                                                                         \
        float m_ = g_stats[(SIDX) * HD + tid] * (1.0f / (float)BD);           \
        float e2_ = g_stats[((SIDX) + 1) * HD + tid] * (1.0f / (float)BD);    \
        float rs_ = rsqrtf(e2_ - m_ * m_ + 1e-5f);                            \
        float sc_ = rs_ * (G)[tid];                                           \
        sScale[tid] = sc_;                                                    \
        sShift[tid] = (B)[tid] - m_ * sc_;                                    \
    }

#define BIAS4(DST, SRCP)                                                      \
    float2 DST[4];                                                            \
    _Pragma("unroll") for (int i_ = 0; i_ < 4; i_++)                          \
        DST[i_] = *(const float2*)((SRCP) + ncol0 + wn * 32 + i_ * 8 + (lane & 3) * 2);

// ---------------- prep kernels ----------------

__global__ void __launch_bounds__(NTH) k0_prep(
    const float* __restrict__ Wx, const float* __restrict__ bx,
    const float* __restrict__ Wi, const float* __restrict__ bi,
    const float* __restrict__ WC, const float* __restrict__ bC) {
    int h = threadIdx.x;
    if (blockIdx.x < HD) {
        __shared__ float sA[HD];
        sA[h] = Wx[blockIdx.x * HD + h];
        __syncthreads();
        float aI = 0.0f, aC = 0.0f;
#pragma unroll 4
        for (int k = 0; k < HD; k++) {
            float a = sA[k];
            aI = fmaf(a, Wi[k * HD + h], aI);
            aC = fmaf(a, WC[k * HD + h], aC);
        }
        g_WxWi[blockIdx.x * HD + h] = aI;
        g_WxWC[blockIdx.x * HD + h] = aC;
    } else {
        float aI = bi[h], aC = bC[h];
        for (int k = 0; k < HD; k++) {
            float a = bx[k];
            aI = fmaf(a, Wi[k * HD + h], aI);
            aC = fmaf(a, WC[k * HD + h], aC);
        }
        g_bxWi[h] = aI;
        g_bxWC[h] = aC;
#pragma unroll
        for (int s = 0; s < 6; s++) g_stats[s * HD + h] = 0.0f;
    }
}

// weights -> transposed [N][K] bf16 hi/lo, chunked by K=64, XOR-swizzled 128B rows
__global__ void __launch_bounds__(NTH) kW(
    const float* __restrict__ Wx, const float* __restrict__ Wh,
    const float* __restrict__ Wf, const float* __restrict__ WLC,
    const float* __restrict__ Wo) {
    int k = blockIdx.x, m = blockIdx.y, n = threadIdx.x;
    const float* src;
    switch (m) {
        case 0: src = Wx; break;
        case 1: src = Wh; break;
        case 2: src = Wf; break;
        case 3: src = g_WxWC; break;
        case 4: src = g_WxWi; break;
        case 5: src = WLC; break;
        default: src = Wo; break;
    }
    float val = src[k * HD + n];
    __nv_bfloat16 h = __float2bfloat16(val);
    __nv_bfloat16 l = __float2bfloat16(val - __bfloat162float(h));
    int chunk = k >> 6, kk = k & 63;
    uint32_t off = (uint32_t)chunk * 32768 + (uint32_t)n * 128 + ((kk * 2) ^ ((n & 7) << 4));
    *(__nv_bfloat16*)((char*)g_Wimg[m][0] + off) = h;
    *(__nv_bfloat16*)((char*)g_Wimg[m][1] + off) = l;
}

// ---------------- GEMM kernels ----------------

// k1a: LC_raw = X@Wx + pLC@Wh + (bx+bh) -> g_scr1; stats0
__global__ void __launch_bounds__(NTH, 2) k1a(
    const float* __restrict__ X, const float* __restrict__ pLC,
    const float* __restrict__ bx, const float* __restrict__ bh_) {
    GEMM_PROLOG;
    A_CPASYNC(X, 0);
#pragma unroll 1
    for (int c = 0; c < 8; c++) {
        PIPE_WAIT_SYNC;  // rawA_c ready
        int mat = (c < 4) ? 0 : 1;
        B_CPASYNC(g_Wimg[mat][0], g_Wimg[mat][1], c & 3);
        A_TRANS_PLAIN;
        PIPE_WAIT_SYNC;  // B ready; raw buffer free
        if (c < 7) {
            const float* nsrc = (c + 1 < 4) ? X : pLC;
            A_CPASYNC(nsrc, ((c + 1) & 3) * 64);
        }
        COMPUTE_CHUNK;
    }
    BIAS4(b1, bx); BIAS4(b2, bh_);
    STATS_DECL;
    EPI_BEGIN;
    vx += b1[ni].x + b2[ni].x;
    vy += b1[ni].y + b2[ni].y;
    STATS_ACC;
    EPI_END_STORE(g_scr1);
    STATS_REDUCE(0);
}

// k1b: base = sigmoid(pC@Wf+bf)*cell + X@WxWC + bxWC -> sec2 (mid-transform at c==3)
__global__ void __launch_bounds__(NTH, 2) k1b(
    const float* __restrict__ pC, const float* __restrict__ X,
    const float* __restrict__ bf_, const float* __restrict__ cell, float* out) {
    GEMM_PROLOG;
    A_CPASYNC(pC, 0);
#pragma unroll 1
    for (int c = 0; c < 8; c++) {
        PIPE_WAIT_SYNC;
        int mat = (c < 4) ? 2 : 3;
        B_CPASYNC(g_Wimg[mat][0], g_Wimg[mat][1], c & 3);
        A_TRANS_PLAIN;
        PIPE_WAIT_SYNC;
        if (c < 7) {
            const float* nsrc = (c + 1 < 4) ? pC : X;
            A_CPASYNC(nsrc, ((c + 1) & 3) * 64);
        }
        COMPUTE_CHUNK;
        if (c == 3) {
            BIAS4(bfv, bf_);
            EPI_BEGIN;
            float2 cv = *(const float2*)(cell + (size_t)rr * HD + cb);
            vx = sigm(vx + bfv[ni].x) * cv.x;
            vy = sigm(vy + bfv[ni].y) * cv.y;
            EPI_END_ACC;
        }
    }
    BIAS4(bb, g_bxWC);
    EPI_BEGIN;
    vx += bb[ni].x;
    vy += bb[ni].y;
    EPI_END_STORE(out);
}

// k1c: igate = sigmoid(X@WxWi + bxWi) -> sec3
__global__ void __launch_bounds__(NTH, 2) k1c(const float* __restrict__ X, float* out) {
    GEMM_PROLOG;
    A_CPASYNC(X, 0);
#pragma unroll 1
    for (int c = 0; c < 4; c++) {
        PIPE_WAIT_SYNC;
        B_CPASYNC(g_Wimg[4][0], g_Wimg[4][1], c);
        A_TRANS_PLAIN;
        PIPE_WAIT_SYNC;
        if (c < 3) A_CPASYNC(X, (c + 1) * 64);
        COMPUTE_CHUNK;
    }
    BIAS4(bb, g_bxWi);
    EPI_BEGIN;
    vx = sigm(vx + bb[ni].x);
    vy = sigm(vy + bb[ni].y);
    EPI_END_STORE(out);
}

// k2: LC_t = leaky(bn1(g_scr1)) -> sec0; NE_raw = LC_t@WLC + bLC -> g_scr2; stats2
__global__ void __launch_bounds__(NTH, 2) k2(
    float* out_lct, const float* __restrict__ bLC,
    const float* __restrict__ g1, const float* __restrict__ be1) {
    GEMM_PROLOG;
    BN_PREP(0, g1, be1);
    A_CPASYNC(g_scr1, 0);
#pragma unroll 1
    for (int c = 0; c < 4; c++) {
        PIPE_WAIT_SYNC;
        B_CPASYNC(g_Wimg[5][0], g_Wimg[5][1], c);
        A_TRANS_BN(out_lct, c * 64);
        PIPE_WAIT_SYNC;
        if (c < 3) A_CPASYNC(g_scr1, (c + 1) * 64);
        COMPUTE_CHUNK;
    }
    BIAS4(bb, bLC);
    STATS_DECL;
    EPI_BEGIN;
    vx += bb[ni].x;
    vy += bb[ni].y;
    STATS_ACC;
    EPI_END_STORE(g_scr2);
    STATS_REDUCE(2);
}

// k3: NE_t = leaky(bn2(g_scr2)) -> sec1; new_cell = base + ig*0.1*(NE_t@WLC+bLC) -> sec4; stats4
__global__ void __launch_bounds__(NTH, 2) k3(
    float* out_nc, float* out_net, const float* __restrict__ bLC,
    const float* __restrict__ base, const float* __restrict__ ig,
    const float* __restrict__ g2, const float* __restrict__ be2) {
    GEMM_PROLOG;
    BN_PREP(2, g2, be2);
    A_CPASYNC(g_scr2, 0);
#pragma unroll 1
    for (int c = 0; c < 4; c++) {
        PIPE_WAIT_SYNC;
        B_CPASYNC(g_Wimg[5][0], g_Wimg[5][1], c);
        A_TRANS_BN(out_net, c * 64);
        PIPE_WAIT_SYNC;
        if (c < 3) A_CPASYNC(g_scr2, (c + 1) * 64);
        COMPUTE_CHUNK;
    }
    BIAS4(bb, bLC);
    STATS_DECL;
    EPI_BEGIN;
    float2 bv = *(const float2*)(base + (size_t)rr * HD + cb);
    float2 iv = *(const float2*)(ig + (size_t)rr * HD + cb);
    vx = fmaf(iv.x * 0.1f, vx + bb[ni].x, bv.x);
    vy = fmaf(iv.y * 0.1f, vy + bb[ni].y, bv.y);
    STATS_ACC;
    EPI_END_STORE(out_nc);
    STATS_REDUCE(4);
}

// k4: C_t = leaky(bn3(sec4)) -> sec2; p = (LC_t+C_t+NE_t)@WP;
//     Pupil = sigmoid(C_t@Wo+bo)*(p+bP) -> sec3
__global__ void __launch_bounds__(NTH, 2) k4(
    const float* __restrict__ ncell, float* out_ct,
    const float* __restrict__ lct, const float* __restrict__ net,
    const float* __restrict__ bo, const float* __restrict__ WP,
    const float* __restrict__ bP, const float* __restrict__ g3,
    const float* __restrict__ be3, float* out_pupil) {
    GEMM_PROLOG;
    BN_PREP(4, g3, be3);
    float* sWP = (float*)(smem + OFF_WP);
    float* p_s = (float*)(smem + OFF_PS);
    sWP[tid] = WP[tid];
    if (tid < MT) p_s[tid] = 0.0f;
    float pv[8];
#pragma unroll
    for (int i = 0; i < 8; i++) pv[i] = 0.0f;
    A_CPASYNC(ncell, 0);
#pragma unroll 1
    for (int c = 0; c < 4; c++) {
        PIPE_WAIT_SYNC;
        B_CPASYNC(g_Wimg[6][0], g_Wimg[6][1], c);
        A_TRANS_TP(out_ct, lct, net, c * 64);
        PIPE_WAIT_SYNC;
        if (c < 3) A_CPASYNC(ncell, (c + 1) * 64);
        COMPUTE_CHUNK;
    }
    {
        const int crr = tid >> 4;
#pragma unroll
        for (int ii = 0; ii < 8; ii++) atomicAdd(&p_s[crr + ii * 16], pv[ii]);
    }
    __syncthreads();
    float bP0 = bP[0];
    BIAS4(bb, bo);
    EPI_BEGIN;
    float pr = p_s[rr - row0] + bP0;
    vx = sigm(vx + bb[ni].x) * pr;
    vy = sigm(vy + bb[ni].y) * pr;
    EPI_END_STORE(out_pupil);
}

// ---------------- launch ----------------

extern "C" void kernel_launch(void* const* d_in, const int* in_sizes, int n_in,
                              void* d_out, int out_size) {
    (void)in_sizes; (void)n_in; (void)out_size;
    const float* X    = (const float*)d_in[0];
    const float* pLC  = (const float*)d_in[1];
    const float* pC   = (const float*)d_in[2];
    const float* cell = (const float*)d_in[3];
    const float* Wx = (const float*)d_in[4];   const float* bx = (const float*)d_in[5];
    const float* Wh = (const float*)d_in[6];   const float* bh = (const float*)d_in[7];
    const float* WLC = (const float*)d_in[8];  const float* bLC = (const float*)d_in[9];
    const float* WC = (const float*)d_in[10];  const float* bC = (const float*)d_in[11];
    const float* WP = (const float*)d_in[12];  const float* bP = (const float*)d_in[13];
    const float* Wf = (const float*)d_in[14];  const float* bf = (const float*)d_in[15];
    const float* Wi = (const float*)d_in[16];  const float* bi = (const float*)d_in[17];
    const float* Wo = (const float*)d_in[18];  const float* bo = (const float*)d_in[19];
    const float* g1 = (const float*)d_in[20];  const float* be1 = (const float*)d_in[21];
    const float* g2 = (const float*)d_in[22];  const float* be2 = (const float*)d_in[23];
    const float* g3 = (const float*)d_in[24];  const float* be3 = (const float*)d_in[25];

    float* o = (float*)d_out;
    const size_t SEC = (size_t)BD * HD;
    float* sLC = o;            // LC_t   (written by k2)
    float* sNE = o + SEC;      // NE_t   (written by k3)
    float* sCT = o + 2 * SEC;  // C_t    (base until k3 consumes it; k4 writes C_t)
    float* sPU = o + 3 * SEC;  // Pupil  (igate until k3; k4 writes Pupil)
    float* sNC = o + 4 * SEC;  // new_cell (written by k3)

    // idempotent; called every time (no static guards per harness contract)
    cudaFuncSetAttribute(k1a, cudaFuncAttributeMaxDynamicSharedMemorySize, SMEM_REQ);
    cudaFuncSetAttribute(k1b, cudaFuncAttributeMaxDynamicSharedMemorySize, SMEM_REQ);
    cudaFuncSetAttribute(k1c, cudaFuncAttributeMaxDynamicSharedMemorySize, SMEM_REQ);
    cudaFuncSetAttribute(k2, cudaFuncAttributeMaxDynamicSharedMemorySize, SMEM_REQ);
    cudaFuncSetAttribute(k3, cudaFuncAttributeMaxDynamicSharedMemorySize, SMEM_REQ);
    cudaFuncSetAttribute(k4, cudaFuncAttributeMaxDynamicSharedMemorySize, SMEM_REQ);

    dim3 blk(NTH);
    dim3 grd(BD / MT, HD / NT);

    k0_prep<<<HD + 1, NTH>>>(Wx, bx, Wi, bi, WC, bC);
    kW<<<dim3(HD, 7), NTH>>>(Wx, Wh, Wf, WLC, Wo);
    k1a<<<grd, blk, SMEM_REQ>>>(X, pLC, bx, bh);
    k1b<<<grd, blk, SMEM_REQ>>>(pC, X, bf, cell, sCT);
    k1c<<<grd, blk, SMEM_REQ>>>(X, sPU);
    k2<<<grd, blk, SMEM_REQ>>>(sLC, bLC, g1, be1);
    k3<<<grd, blk, SMEM_REQ>>>(sNC, sNE, bLC, sCT, sPU, g2, be2);
    k4<<<grd, blk, SMEM_REQ>>>(sNC, sCT, sLC, sNE, bo, WP, bP, g3, be3, sPU);
}